// round 3
// baseline (speedup 1.0000x reference)
#include <cuda_runtime.h>
#include <cuda_bf16.h>
#include <cstdint>

#define BB 4
#define NN 50000
#define EE 800000

// ---------------------------------------------------------------------------
// Scratch (static device globals; runtime allocation is forbidden)
// ---------------------------------------------------------------------------
__device__ float4 g_ya4[BB * NN * 8];   // ya = x@W1[0:32] + b1   (B,N,32)
__device__ float4 g_yb4[BB * NN * 8];   // yb = x@W1[32:64]       (B,N,32)
__device__ float4 g_acc4[BB * NN * 8];  // node accumulator, 30 used, padded to 32
__device__ float  g_part[512];          // partial sums for edge_attr stats
__device__ float  g_stat[2];            // mean, rstd
__device__ int    g_is64;               // 1 if edge_index is int64, 0 if int32

__device__ __forceinline__ float sigf(float x) {
    return __fdividef(1.0f, 1.0f + __expf(-x));
}

__device__ __forceinline__ void red4(float* p, float a, float b, float c, float d) {
    asm volatile("red.global.add.v4.f32 [%0], {%1,%2,%3,%4};"
                 :: "l"(p), "f"(a), "f"(b), "f"(c), "f"(d) : "memory");
}

// ---------------------------------------------------------------------------
// 0. detect edge_index width: int32 data read as int64 pairs gives values
//    >= 2^32 with overwhelming probability (indices are uniform in [0,50000)).
// ---------------------------------------------------------------------------
__global__ void k_detect(const void* ei) {
    const long long* p = (const long long*)ei;
    int ok64 = 1;
    for (int j = 0; j < 16; j++) {
        long long v = p[j];
        if (v < 0 || v >= (long long)NN) ok64 = 0;
    }
    g_is64 = ok64;
}

// ---------------------------------------------------------------------------
// 1a. edge_attr stats: per-block partial (sum, sumsq). Deterministic tree.
// ---------------------------------------------------------------------------
__global__ void k_stat1(const float* __restrict__ ea) {
    __shared__ float ss[256], sq[256];
    int tid = threadIdx.x;
    float s = 0.f, q = 0.f;
    for (int i = blockIdx.x * 256 + tid; i < EE; i += 256 * 256) {
        float v = __ldg(&ea[i]);
        s += v;
        q += v * v;
    }
    ss[tid] = s; sq[tid] = q;
    __syncthreads();
    for (int o = 128; o > 0; o >>= 1) {
        if (tid < o) { ss[tid] += ss[tid + o]; sq[tid] += sq[tid + o]; }
        __syncthreads();
    }
    if (tid == 0) {
        g_part[blockIdx.x]       = ss[0];
        g_part[256 + blockIdx.x] = sq[0];
    }
}

// 1b. combine partials -> mean, rstd (ddof=1)
__global__ void k_stat2() {
    __shared__ float ss[256], sq[256];
    int tid = threadIdx.x;
    ss[tid] = g_part[tid];
    sq[tid] = g_part[256 + tid];
    __syncthreads();
    for (int o = 128; o > 0; o >>= 1) {
        if (tid < o) { ss[tid] += ss[tid + o]; sq[tid] += sq[tid + o]; }
        __syncthreads();
    }
    if (tid == 0) {
        float s = ss[0], q = sq[0];
        float mean = s / (float)EE;
        float var  = (q - s * s / (float)EE) / (float)(EE - 1);
        g_stat[0] = mean;
        g_stat[1] = rsqrtf(var);
    }
}

// ---------------------------------------------------------------------------
// 2. zero the node accumulator
// ---------------------------------------------------------------------------
__global__ void k_zero() {
    int i = blockIdx.x * blockDim.x + threadIdx.x;
    if (i < BB * NN * 8) g_acc4[i] = make_float4(0.f, 0.f, 0.f, 0.f);
}

// ---------------------------------------------------------------------------
// 3. precompute ya = x@W1a + b1, yb = x@W1b  (warp per row, weights in regs)
// ---------------------------------------------------------------------------
__global__ void __launch_bounds__(256) k_pre(const float* __restrict__ x,
                                             const float* __restrict__ W1,
                                             const float* __restrict__ b1) {
    int lane   = threadIdx.x & 31;
    int warp   = (blockIdx.x * blockDim.x + threadIdx.x) >> 5;
    int nwarps = (gridDim.x * blockDim.x) >> 5;

    float wa[32], wb[32];
#pragma unroll
    for (int k = 0; k < 32; k++) {
        wa[k] = __ldg(&W1[k * 32 + lane]);          // W1 rows 0..31
        wb[k] = __ldg(&W1[(32 + k) * 32 + lane]);   // W1 rows 32..63
    }
    float bv = __ldg(&b1[lane]);

    float* ya = reinterpret_cast<float*>(g_ya4);
    float* yb = reinterpret_cast<float*>(g_yb4);

    for (int row = warp; row < BB * NN; row += nwarps) {
        float xv = __ldg(&x[row * 32 + lane]);
        float sa = bv, sb = 0.f;
#pragma unroll
        for (int k = 0; k < 32; k++) {
            float xk = __shfl_sync(0xffffffffu, xv, k);
            sa = fmaf(xk, wa[k], sa);
            sb = fmaf(xk, wb[k], sb);
        }
        ya[row * 32 + lane] = sa;
        yb[row * 32 + lane] = sb;
    }
}

// ---------------------------------------------------------------------------
// 4. main edge kernel: thread = (edge, batch).
//    h1 = sig(ya[src] + yb[tgt] + ean*W1c); h2 = sig(h1@W2 + b2);
//    red(+h2 -> tgt), red(-h2 -> src)
// ---------------------------------------------------------------------------
__global__ void __launch_bounds__(256) k_edge(const void* __restrict__ ei,
                                              const float* __restrict__ ea,
                                              const float* __restrict__ W1,
                                              const float* __restrict__ W2,
                                              const float* __restrict__ b2) {
    __shared__ float  w1c[32];
    __shared__ float  b2s[32];
    __shared__ float4 w2s[32][8];   // W2 padded (32 x 32)

    int tid = threadIdx.x;
    if (tid < 32) w1c[tid] = W1[64 * 32 + tid];
    if (tid < 32) b2s[tid] = (tid < 30) ? b2[tid] : 0.f;
    for (int i = tid; i < 32 * 32; i += 256) {
        int k = i >> 5, j = i & 31;
        reinterpret_cast<float*>(w2s)[k * 32 + j] = (j < 30) ? W2[k * 30 + j] : 0.f;
    }
    __syncthreads();

    int e = blockIdx.x * 256 + tid;
    if (e >= EE) return;
    int b = blockIdx.y;

    int src, tgt;
    if (g_is64) {
        const long long* p = (const long long*)ei;
        src = (int)__ldg(&p[e]);
        tgt = (int)__ldg(&p[EE + e]);
    } else {
        const int* p = (const int*)ei;
        src = __ldg(&p[e]);
        tgt = __ldg(&p[EE + e]);
    }
    // defensive clamp: a wrong decode shows as rel_err, not an opaque crash
    src = min(max(src, 0), NN - 1);
    tgt = min(max(tgt, 0), NN - 1);

    float ean = (__ldg(&ea[e]) - g_stat[0]) * g_stat[1];

    const float4* pa = &g_ya4[(b * NN + src) * 8];
    const float4* pb = &g_yb4[(b * NN + tgt) * 8];

    float h1[32];
#pragma unroll
    for (int q = 0; q < 8; q++) {
        float4 a = pa[q];
        float4 c = pb[q];
        h1[4 * q + 0] = sigf(a.x + c.x + ean * w1c[4 * q + 0]);
        h1[4 * q + 1] = sigf(a.y + c.y + ean * w1c[4 * q + 1]);
        h1[4 * q + 2] = sigf(a.z + c.z + ean * w1c[4 * q + 2]);
        h1[4 * q + 3] = sigf(a.w + c.w + ean * w1c[4 * q + 3]);
    }

    float acc[30];
#pragma unroll
    for (int j = 0; j < 30; j++) acc[j] = b2s[j];

#pragma unroll
    for (int k = 0; k < 32; k++) {
        float h = h1[k];
#pragma unroll
        for (int q = 0; q < 8; q++) {
            float4 w = w2s[k][q];
            if (4 * q + 0 < 30) acc[4 * q + 0] = fmaf(h, w.x, acc[4 * q + 0]);
            if (4 * q + 1 < 30) acc[4 * q + 1] = fmaf(h, w.y, acc[4 * q + 1]);
            if (4 * q + 2 < 30) acc[4 * q + 2] = fmaf(h, w.z, acc[4 * q + 2]);
            if (4 * q + 3 < 30) acc[4 * q + 3] = fmaf(h, w.w, acc[4 * q + 3]);
        }
    }

    float h2[32];
#pragma unroll
    for (int j = 0; j < 30; j++) h2[j] = sigf(acc[j]);
    h2[30] = 0.f; h2[31] = 0.f;

    float* at = reinterpret_cast<float*>(&g_acc4[(b * NN + tgt) * 8]);
    float* as = reinterpret_cast<float*>(&g_acc4[(b * NN + src) * 8]);
#pragma unroll
    for (int q = 0; q < 8; q++) {
        red4(at + 4 * q,  h2[4 * q + 0],  h2[4 * q + 1],  h2[4 * q + 2],  h2[4 * q + 3]);
        red4(as + 4 * q, -h2[4 * q + 0], -h2[4 * q + 1], -h2[4 * q + 2], -h2[4 * q + 3]);
    }
}

// ---------------------------------------------------------------------------
// 5. final: out = sigmoid(acc[:, :30] @ W3 + b3)   (warp per row)
// ---------------------------------------------------------------------------
__global__ void __launch_bounds__(256) k_out(const float* __restrict__ W3,
                                             const float* __restrict__ b3,
                                             float* __restrict__ out) {
    int lane   = threadIdx.x & 31;
    int warp   = (blockIdx.x * blockDim.x + threadIdx.x) >> 5;
    int nwarps = (gridDim.x * blockDim.x) >> 5;

    float w3r[30];
#pragma unroll
    for (int k = 0; k < 30; k++) w3r[k] = __ldg(&W3[k * 32 + lane]);
    float bv = __ldg(&b3[lane]);

    const float* accf = reinterpret_cast<const float*>(g_acc4);

    for (int row = warp; row < BB * NN; row += nwarps) {
        float av = accf[row * 32 + lane];   // lanes 30,31 hold padding (unused)
        float s = bv;
#pragma unroll
        for (int k = 0; k < 30; k++) {
            s = fmaf(__shfl_sync(0xffffffffu, av, k), w3r[k], s);
        }
        out[row * 32 + lane] = sigf(s);
    }
}

// ---------------------------------------------------------------------------
// launch: resolve inputs by element count (robust to metadata ordering).
//   x: 6,400,000   edge_index: 1,600,000   edge_attr: 800,000
//   W1: 2080   W2/W3: 960 (W2 first)   b1/b3: 32 (b1 first)   b2: 30
// ---------------------------------------------------------------------------
extern "C" void kernel_launch(void* const* d_in, const int* in_sizes, int n_in,
                              void* d_out, int out_size) {
    const float *x = 0, *ea = 0, *W1 = 0, *b1 = 0, *W2 = 0, *b2 = 0, *W3 = 0, *b3 = 0;
    const void* ei = 0;
    int nW = 0, nb = 0;
    for (int i = 0; i < n_in; i++) {
        switch (in_sizes[i]) {
            case 6400000: x  = (const float*)d_in[i]; break;
            case 1600000: ei = d_in[i];               break;
            case 800000:  ea = (const float*)d_in[i]; break;
            case 2080:    W1 = (const float*)d_in[i]; break;
            case 960:     if (nW++ == 0) W2 = (const float*)d_in[i];
                          else           W3 = (const float*)d_in[i]; break;
            case 32:      if (nb++ == 0) b1 = (const float*)d_in[i];
                          else           b3 = (const float*)d_in[i]; break;
            case 30:      b2 = (const float*)d_in[i]; break;
        }
    }
    float* out = (float*)d_out;

    k_detect<<<1, 1>>>(ei);
    k_stat1<<<256, 256>>>(ea);
    k_stat2<<<1, 256>>>();
    k_zero<<<(BB * NN * 8 + 255) / 256, 256>>>();
    k_pre<<<512, 256>>>(x, W1, b1);

    dim3 egrid((EE + 255) / 256, BB);
    k_edge<<<egrid, 256>>>(ei, ea, W1, W2, b2);

    k_out<<<512, 256>>>(W3, b3, out);
}

// round 4
// speedup vs baseline: 1.0406x; 1.0406x over previous
#include <cuda_runtime.h>
#include <cuda_bf16.h>
#include <cstdint>

#define BB 4
#define NN 50000
#define EE 800000

// ---------------------------------------------------------------------------
// Scratch (static device globals; runtime allocation is forbidden)
// ---------------------------------------------------------------------------
__device__ float4 g_ya4[BB * NN * 8];   // ya = x@W1[0:32] + b1   (B,N,32)
__device__ float4 g_yb4[BB * NN * 8];   // yb = x@W1[32:64]       (B,N,32)
__device__ float4 g_acc4[BB * NN * 8];  // node accumulator, 30 used, padded to 32
__device__ float  g_part[512];          // partial sums for edge_attr stats
__device__ float  g_stat[2];            // mean, rstd
__device__ int    g_is64;               // 1 if edge_index is int64, 0 if int32

typedef unsigned long long u64;

// ---- packed f32x2 helpers (sm_103a FFMA2 path; only reachable via PTX) ----
__device__ __forceinline__ u64 pk2(float lo, float hi) {
    u64 r; asm("mov.b64 %0,{%1,%2};" : "=l"(r) : "f"(lo), "f"(hi)); return r;
}
__device__ __forceinline__ void upk2(float& lo, float& hi, u64 v) {
    asm("mov.b64 {%0,%1},%2;" : "=f"(lo), "=f"(hi) : "l"(v));
}
__device__ __forceinline__ u64 fma2(u64 a, u64 b, u64 c) {
    u64 d; asm("fma.rn.f32x2 %0,%1,%2,%3;" : "=l"(d) : "l"(a), "l"(b), "l"(c)); return d;
}
__device__ __forceinline__ u64 add2(u64 a, u64 b) {
    u64 d; asm("add.rn.f32x2 %0,%1,%2;" : "=l"(d) : "l"(a), "l"(b)); return d;
}

__device__ __forceinline__ float sigf(float x) {
    return __fdividef(1.0f, 1.0f + __expf(-x));
}
__device__ __forceinline__ float negf(float x) {           // sign flip on ALU pipe
    return __int_as_float(__float_as_int(x) ^ 0x80000000);
}

__device__ __forceinline__ void red4(float* p, float a, float b, float c, float d) {
    asm volatile("red.global.add.v4.f32 [%0], {%1,%2,%3,%4};"
                 :: "l"(p), "f"(a), "f"(b), "f"(c), "f"(d) : "memory");
}

// ---------------------------------------------------------------------------
// 0. detect edge_index width: int32 data read as int64 pairs gives values
//    outside [0,N) with overwhelming probability.
// ---------------------------------------------------------------------------
__global__ void k_detect(const void* ei) {
    const long long* p = (const long long*)ei;
    int ok64 = 1;
    for (int j = 0; j < 16; j++) {
        long long v = p[j];
        if (v < 0 || v >= (long long)NN) ok64 = 0;
    }
    g_is64 = ok64;
}

// ---------------------------------------------------------------------------
// 1a. edge_attr stats: per-block partial (sum, sumsq). Deterministic tree.
// ---------------------------------------------------------------------------
__global__ void k_stat1(const float* __restrict__ ea) {
    __shared__ float ss[256], sq[256];
    int tid = threadIdx.x;
    float s = 0.f, q = 0.f;
    for (int i = blockIdx.x * 256 + tid; i < EE; i += 256 * 256) {
        float v = __ldg(&ea[i]);
        s += v;
        q += v * v;
    }
    ss[tid] = s; sq[tid] = q;
    __syncthreads();
    for (int o = 128; o > 0; o >>= 1) {
        if (tid < o) { ss[tid] += ss[tid + o]; sq[tid] += sq[tid + o]; }
        __syncthreads();
    }
    if (tid == 0) {
        g_part[blockIdx.x]       = ss[0];
        g_part[256 + blockIdx.x] = sq[0];
    }
}

// 1b. combine partials -> mean, rstd (ddof=1)
__global__ void k_stat2() {
    __shared__ float ss[256], sq[256];
    int tid = threadIdx.x;
    ss[tid] = g_part[tid];
    sq[tid] = g_part[256 + tid];
    __syncthreads();
    for (int o = 128; o > 0; o >>= 1) {
        if (tid < o) { ss[tid] += ss[tid + o]; sq[tid] += sq[tid + o]; }
        __syncthreads();
    }
    if (tid == 0) {
        float s = ss[0], q = sq[0];
        float mean = s / (float)EE;
        float var  = (q - s * s / (float)EE) / (float)(EE - 1);
        g_stat[0] = mean;
        g_stat[1] = rsqrtf(var);
    }
}

// ---------------------------------------------------------------------------
// 2. zero the node accumulator
// ---------------------------------------------------------------------------
__global__ void k_zero() {
    int i = blockIdx.x * blockDim.x + threadIdx.x;
    if (i < BB * NN * 8) g_acc4[i] = make_float4(0.f, 0.f, 0.f, 0.f);
}

// ---------------------------------------------------------------------------
// 3. precompute ya = x@W1a + b1, yb = x@W1b  (warp/row; packed (sa,sb) FMA)
// ---------------------------------------------------------------------------
__global__ void __launch_bounds__(256) k_pre(const float* __restrict__ x,
                                             const float* __restrict__ W1,
                                             const float* __restrict__ b1) {
    int lane   = threadIdx.x & 31;
    int warp   = (blockIdx.x * blockDim.x + threadIdx.x) >> 5;
    int nwarps = (gridDim.x * blockDim.x) >> 5;

    u64 wab[32];
#pragma unroll
    for (int k = 0; k < 32; k++) {
        wab[k] = pk2(__ldg(&W1[k * 32 + lane]), __ldg(&W1[(32 + k) * 32 + lane]));
    }
    u64 binit = pk2(__ldg(&b1[lane]), 0.f);

    float* ya = reinterpret_cast<float*>(g_ya4);
    float* yb = reinterpret_cast<float*>(g_yb4);

    for (int row = warp; row < BB * NN; row += nwarps) {
        float xv = __ldg(&x[row * 32 + lane]);
        u64 acc = binit;
#pragma unroll
        for (int k = 0; k < 32; k++) {
            float xk = __shfl_sync(0xffffffffu, xv, k);
            acc = fma2(pk2(xk, xk), wab[k], acc);
        }
        float sa, sb;
        upk2(sa, sb, acc);
        ya[row * 32 + lane] = sa;
        yb[row * 32 + lane] = sb;
    }
}

// ---------------------------------------------------------------------------
// 4. main edge kernel: thread = (edge, batch).  Packed-f32x2 layer 2.
// ---------------------------------------------------------------------------
__global__ void __launch_bounds__(256) k_edge(const void* __restrict__ ei,
                                              const float* __restrict__ ea,
                                              const float* __restrict__ W1,
                                              const float* __restrict__ W2,
                                              const float* __restrict__ b2) {
    __shared__ u64 w1cp[16];      // W1 edge-attr row, packed pairs
    __shared__ u64 b2p[16];       // b2 packed (15 pairs + 1 pad)
    __shared__ u64 w2p[32][16];   // W2[k] padded to 16 pairs (128B rows)

    int tid = threadIdx.x;
    if (tid < 16) {
        w1cp[tid] = pk2(W1[64 * 32 + 2 * tid], W1[64 * 32 + 2 * tid + 1]);
        float blo = (2 * tid     < 30) ? b2[2 * tid]     : 0.f;
        float bhi = (2 * tid + 1 < 30) ? b2[2 * tid + 1] : 0.f;
        b2p[tid] = pk2(blo, bhi);
    }
    for (int i = tid; i < 32 * 32; i += 256) {
        int k = i >> 5, j = i & 31;
        reinterpret_cast<float*>(w2p)[k * 32 + j] = (j < 30) ? W2[k * 30 + j] : 0.f;
    }
    __syncthreads();

    int e = blockIdx.x * 256 + tid;
    if (e >= EE) return;
    int b = blockIdx.y;

    int src, tgt;
    if (g_is64) {
        const long long* p = (const long long*)ei;
        src = (int)__ldg(&p[e]);
        tgt = (int)__ldg(&p[EE + e]);
    } else {
        const int* p = (const int*)ei;
        src = __ldg(&p[e]);
        tgt = __ldg(&p[EE + e]);
    }
    src = min(max(src, 0), NN - 1);
    tgt = min(max(tgt, 0), NN - 1);

    float ean = (__ldg(&ea[e]) - g_stat[0]) * g_stat[1];
    u64 ean2 = pk2(ean, ean);

    // gather as packed pairs directly: LDG.128 quads alias f32x2 pairs
    const ulonglong2* pa = reinterpret_cast<const ulonglong2*>(&g_ya4[(b * NN + src) * 8]);
    const ulonglong2* pb = reinterpret_cast<const ulonglong2*>(&g_yb4[(b * NN + tgt) * 8]);

    float h1[32];
#pragma unroll
    for (int q = 0; q < 8; q++) {
        ulonglong2 A = pa[q];
        ulonglong2 C = pb[q];
        u64 t0 = fma2(ean2, w1cp[2 * q],     add2(A.x, C.x));
        u64 t1 = fma2(ean2, w1cp[2 * q + 1], add2(A.y, C.y));
        float v0, v1, v2, v3;
        upk2(v0, v1, t0);
        upk2(v2, v3, t1);
        h1[4 * q + 0] = sigf(v0);
        h1[4 * q + 1] = sigf(v1);
        h1[4 * q + 2] = sigf(v2);
        h1[4 * q + 3] = sigf(v3);
    }

    u64 acc[15];
#pragma unroll
    for (int j = 0; j < 15; j++) acc[j] = b2p[j];

#pragma unroll
    for (int k = 0; k < 32; k++) {
        u64 hh = pk2(h1[k], h1[k]);
        const ulonglong2* wr = reinterpret_cast<const ulonglong2*>(w2p[k]);
#pragma unroll
        for (int q = 0; q < 8; q++) {
            ulonglong2 w = wr[q];
            acc[2 * q] = fma2(hh, w.x, acc[2 * q]);
            if (q < 7) acc[2 * q + 1] = fma2(hh, w.y, acc[2 * q + 1]);
        }
    }

    float h2[32];
#pragma unroll
    for (int j = 0; j < 15; j++) {
        float lo, hi;
        upk2(lo, hi, acc[j]);
        h2[2 * j]     = sigf(lo);
        h2[2 * j + 1] = sigf(hi);
    }
    h2[30] = 0.f; h2[31] = 0.f;

    float* at = reinterpret_cast<float*>(&g_acc4[(b * NN + tgt) * 8]);
    float* as = reinterpret_cast<float*>(&g_acc4[(b * NN + src) * 8]);
#pragma unroll
    for (int q = 0; q < 8; q++) {
        red4(at + 4 * q, h2[4 * q + 0], h2[4 * q + 1], h2[4 * q + 2], h2[4 * q + 3]);
        red4(as + 4 * q, negf(h2[4 * q + 0]), negf(h2[4 * q + 1]),
                         negf(h2[4 * q + 2]), negf(h2[4 * q + 3]));
    }
}

// ---------------------------------------------------------------------------
// 5. final: out = sigmoid(acc[:, :30] @ W3 + b3)   (warp per row)
// ---------------------------------------------------------------------------
__global__ void __launch_bounds__(256) k_out(const float* __restrict__ W3,
                                             const float* __restrict__ b3,
                                             float* __restrict__ out) {
    int lane   = threadIdx.x & 31;
    int warp   = (blockIdx.x * blockDim.x + threadIdx.x) >> 5;
    int nwarps = (gridDim.x * blockDim.x) >> 5;

    float w3r[30];
#pragma unroll
    for (int k = 0; k < 30; k++) w3r[k] = __ldg(&W3[k * 32 + lane]);
    float bv = __ldg(&b3[lane]);

    const float* accf = reinterpret_cast<const float*>(g_acc4);

    for (int row = warp; row < BB * NN; row += nwarps) {
        float av = accf[row * 32 + lane];   // lanes 30,31 hold padding (unused)
        float s = bv;
#pragma unroll
        for (int k = 0; k < 30; k++) {
            s = fmaf(__shfl_sync(0xffffffffu, av, k), w3r[k], s);
        }
        out[row * 32 + lane] = sigf(s);
    }
}

// ---------------------------------------------------------------------------
// launch: resolve inputs by element count (robust to metadata ordering).
// ---------------------------------------------------------------------------
extern "C" void kernel_launch(void* const* d_in, const int* in_sizes, int n_in,
                              void* d_out, int out_size) {
    const float *x = 0, *ea = 0, *W1 = 0, *b1 = 0, *W2 = 0, *b2 = 0, *W3 = 0, *b3 = 0;
    const void* ei = 0;
    int nW = 0, nb = 0;
    for (int i = 0; i < n_in; i++) {
        switch (in_sizes[i]) {
            case 6400000: x  = (const float*)d_in[i]; break;
            case 1600000: ei = d_in[i];               break;
            case 800000:  ea = (const float*)d_in[i]; break;
            case 2080:    W1 = (const float*)d_in[i]; break;
            case 960:     if (nW++ == 0) W2 = (const float*)d_in[i];
                          else           W3 = (const float*)d_in[i]; break;
            case 32:      if (nb++ == 0) b1 = (const float*)d_in[i];
                          else           b3 = (const float*)d_in[i]; break;
            case 30:      b2 = (const float*)d_in[i]; break;
        }
    }
    float* out = (float*)d_out;

    k_detect<<<1, 1>>>(ei);
    k_stat1<<<256, 256>>>(ea);
    k_stat2<<<1, 256>>>();
    k_zero<<<(BB * NN * 8 + 255) / 256, 256>>>();
    k_pre<<<512, 256>>>(x, W1, b1);

    dim3 egrid((EE + 255) / 256, BB);
    k_edge<<<egrid, 256>>>(ei, ea, W1, W2, b2);

    k_out<<<512, 256>>>(W3, b3, out);
}